// round 3
// baseline (speedup 1.0000x reference)
#include <cuda_runtime.h>
#include <stdint.h>
#include <math.h>

// ---------------- problem constants ----------------
#define T_   128
#define B_   512
#define DIN_ 512
#define H_   512
#define DM_  256
#define HYP_ 256
#define L_   100

// output offsets (floats)
#define OUT_N      ((int64_t)T_*B_*H_)          // 33554432
#define OFF_HT     (OUT_N)                      // 33554432
#define OFF_CT     (OFF_HT + (int64_t)B_*H_)    // 33816576
#define OFF_HHAT   (OFF_CT + (int64_t)B_*H_)    // 34078720  (2*B*HYP zeros follow)

// ---------------- scratch (device globals; no allocation in kernel_launch) ----
__device__ float g_q   [(size_t)T_*B_*HYP_];      // 64 MB
__device__ float g_k   [(size_t)B_*L_*HYP_];      // 52 MB
__device__ float g_att [(size_t)T_*B_*DM_];       // 64 MB
__device__ float g_mpre[(size_t)T_*B_*HYP_];      // 64 MB
__device__ float g_wx  [(size_t)T_*B_*4*H_];      // 512 MB
__device__ float g_WzT [3*4*HYP_*HYP_];
__device__ float g_Wcomp[3*4*H_*HYP_];            // [s][k][h][z]
__device__ float g_bcomp[3*4*H_];
__device__ float g_merged[B_*HYP_];
__device__ float g_D  [(size_t)B_*3*4*H_];        // [b][s][k][h]
__device__ float g_wh [(size_t)B_*4*H_];
__device__ float g_h  [B_*H_];
__device__ float g_c  [B_*H_];

// ---------------- generic SGEMM:  C[m,n] = sum_k A[m,k]*W[n,k] (+bias)(+add)(relu) ----
#define BM 64
#define BN 64
#define BK 16

__global__ void __launch_bounds__(256)
sgemm_nt(const float* __restrict__ A, int lda, int64_t sA,
         const float* __restrict__ W, int ldw, int64_t sW,
         float* __restrict__ C, int ldc, int64_t sC,
         const float* __restrict__ bias,
         const float* __restrict__ addsrc, int ldadd,
         int K, int relu)
{
    __shared__ float As[BK][BM + 4];
    __shared__ float Ws[BK][BN + 4];

    const int bz = blockIdx.z;
    A += bz * sA;  W += bz * sW;  C += bz * sC;

    const int m0 = blockIdx.y * BM;
    const int n0 = blockIdx.x * BN;
    const int tid = threadIdx.x;
    const int tx = tid & 15, ty = tid >> 4;
    const int lr = tid >> 2;            // row 0..63 within tile
    const int lk = (tid & 3) << 2;      // 0,4,8,12

    const float* Ap = A + (int64_t)(m0 + lr) * lda + lk;
    const float* Wp = W + (int64_t)(n0 + lr) * ldw + lk;

    float acc[4][4] = {};

    for (int k0 = 0; k0 < K; k0 += BK) {
        float4 a4 = *(const float4*)(Ap + k0);
        float4 w4 = *(const float4*)(Wp + k0);
        __syncthreads();
        As[lk + 0][lr] = a4.x; As[lk + 1][lr] = a4.y;
        As[lk + 2][lr] = a4.z; As[lk + 3][lr] = a4.w;
        Ws[lk + 0][lr] = w4.x; Ws[lk + 1][lr] = w4.y;
        Ws[lk + 2][lr] = w4.z; Ws[lk + 3][lr] = w4.w;
        __syncthreads();
        #pragma unroll
        for (int kk = 0; kk < BK; kk++) {
            float4 af = *(const float4*)&As[kk][ty << 2];
            float4 wf = *(const float4*)&Ws[kk][tx << 2];
            float a[4] = {af.x, af.y, af.z, af.w};
            float w[4] = {wf.x, wf.y, wf.z, wf.w};
            #pragma unroll
            for (int i = 0; i < 4; i++)
                #pragma unroll
                for (int j = 0; j < 4; j++)
                    acc[i][j] += a[i] * w[j];
        }
    }

    const int nc = n0 + (tx << 2);
    float4 b4 = make_float4(0.f, 0.f, 0.f, 0.f);
    if (bias) b4 = *(const float4*)&bias[nc];
    #pragma unroll
    for (int i = 0; i < 4; i++) {
        const int64_t row = m0 + (ty << 2) + i;
        float4 r;
        r.x = acc[i][0] + b4.x; r.y = acc[i][1] + b4.y;
        r.z = acc[i][2] + b4.z; r.w = acc[i][3] + b4.w;
        if (addsrc) {
            float4 s4 = *(const float4*)&addsrc[row * ldadd + nc];
            r.x += s4.x; r.y += s4.y; r.z += s4.z; r.w += s4.w;
        }
        if (relu) {
            r.x = fmaxf(r.x, 0.f); r.y = fmaxf(r.y, 0.f);
            r.z = fmaxf(r.z, 0.f); r.w = fmaxf(r.w, 0.f);
        }
        *(float4*)&C[row * ldc + nc] = r;
    }
}

// ---------------- fused attention: scores + mask + softmax + attended -----------
__global__ void __launch_bounds__(256)
attn_kernel(const float* __restrict__ q, const float* __restrict__ k,
            const float* __restrict__ meta, const int* __restrict__ inp,
            float* __restrict__ att)
{
    const int tb = blockIdx.x;          // t*B + b
    const int b  = tb & (B_ - 1);
    const int tid = threadIdx.x;
    __shared__ float qs[HYP_];
    __shared__ float sc[128];

    qs[tid] = q[(int64_t)tb * HYP_ + tid] * 0.0625f;   // 1/sqrt(256)
    __syncthreads();

    const int lane = tid & 31, wrp = tid >> 5;
    for (int l = wrp; l < L_; l += 8) {
        const float* kp = k + ((int64_t)b * L_ + l) * HYP_;
        float s = 0.f;
        #pragma unroll
        for (int e = 0; e < HYP_ / 32; e++)
            s += qs[lane + 32 * e] * kp[lane + 32 * e];
        #pragma unroll
        for (int o = 16; o; o >>= 1) s += __shfl_xor_sync(0xffffffffu, s, o);
        if (lane == 0) sc[l] = (inp[b * L_ + l] == 0) ? -1e9f : s;
    }
    __syncthreads();

    if (tid < 32) {
        float v[4]; float m = -3.0e38f;
        #pragma unroll
        for (int j = 0; j < 4; j++) {
            int l = tid + 32 * j;
            v[j] = (l < L_) ? sc[l] : -3.0e38f;
            m = fmaxf(m, v[j]);
        }
        #pragma unroll
        for (int o = 16; o; o >>= 1) m = fmaxf(m, __shfl_xor_sync(0xffffffffu, m, o));
        float s = 0.f;
        #pragma unroll
        for (int j = 0; j < 4; j++) { v[j] = expf(v[j] - m); s += v[j]; }
        #pragma unroll
        for (int o = 16; o; o >>= 1) s += __shfl_xor_sync(0xffffffffu, s, o);
        const float inv = 1.0f / s;
        #pragma unroll
        for (int j = 0; j < 4; j++) {
            int l = tid + 32 * j;
            if (l < L_) sc[l] = v[j] * inv;
        }
    }
    __syncthreads();

    float acc = 0.f;
    const float* mp = meta + (int64_t)b * L_ * DM_ + tid;
    #pragma unroll 4
    for (int l = 0; l < L_; l++) acc += sc[l] * mp[(int64_t)l * DM_];
    att[(int64_t)tb * DM_ + tid] = acc;
}

// ---------------- weight preprocessing ----------------
// WzT[s][k][z][z2] = Wz_s[k*HYP + z2][z]
__global__ void transpose_wz(const float* __restrict__ Wzh, const float* __restrict__ Wzx,
                             const float* __restrict__ Wzb, float* __restrict__ WzT)
{
    int idx = blockIdx.x * 256 + threadIdx.x;            // 3*4*256*256 total
    int s  = idx / (4 * HYP_ * HYP_);
    int r  = idx % (4 * HYP_ * HYP_);
    int kk = r / (HYP_ * HYP_);
    int r2 = r % (HYP_ * HYP_);
    int z  = r2 / HYP_;
    int z2 = r2 % HYP_;
    const float* Wz = (s == 0) ? Wzh : ((s == 1) ? Wzx : Wzb);
    WzT[idx] = Wz[(kk * HYP_ + z2) * HYP_ + z];
}

// bcomp[s=0][k][h] = sum_z bzh[k,z]*Wdh[k,h,z]; s=1 with bzx,Wdx; s=2 = bdb
__global__ void comp_bias(const float* __restrict__ bzh, const float* __restrict__ Wdh,
                          const float* __restrict__ bzx, const float* __restrict__ Wdx,
                          const float* __restrict__ bdb, float* __restrict__ bcomp)
{
    int n = blockIdx.x * 256 + threadIdx.x;   // 6144
    if (n < 2048) {
        int kk = n >> 9;
        float s = 0.f;
        for (int z = 0; z < HYP_; z++) s += bzh[kk * HYP_ + z] * Wdh[n * HYP_ + z];
        bcomp[n] = s;
    } else if (n < 4096) {
        int m = n - 2048; int kk = m >> 9;
        float s = 0.f;
        for (int z = 0; z < HYP_; z++) s += bzx[kk * HYP_ + z] * Wdx[m * HYP_ + z];
        bcomp[n] = s;
    } else {
        bcomp[n] = bdb[n - 4096];
    }
}

__global__ void init_zero(float* __restrict__ h, float* __restrict__ c,
                          float* __restrict__ tail)
{
    int i = blockIdx.x * 256 + threadIdx.x;   // 262144 == B*H == 2*B*HYP
    h[i] = 0.f; c[i] = 0.f; tail[i] = 0.f;
}

// ---------------- fused elementwise + LayerNorm + LSTM cell ----------------
__global__ void __launch_bounds__(512)
lstm_step(const float* __restrict__ D, const float* __restrict__ wh,
          const float* __restrict__ wx, const float* __restrict__ lng,
          const float* __restrict__ lnb, float* __restrict__ h,
          float* __restrict__ c, float* __restrict__ out,
          float* __restrict__ hT, float* __restrict__ cT)
{
    const int b  = blockIdx.x;
    const int hh = threadIdx.x;            // H_ threads
    const int lane = hh & 31, wrp = hh >> 5;
    __shared__ float red[4][16];
    __shared__ float mu_s[4], iv_s[4];

    float y[4];
    #pragma unroll
    for (int k = 0; k < 4; k++) {
        const int idx = k * H_ + hh;
        const int64_t base = (int64_t)b * 6144;
        float dh = D[base + idx];
        float dx = D[base + 2048 + idx];
        float db = D[base + 4096 + idx];
        y[k] = dh * wh[(int64_t)b * 2048 + idx] + dx * wx[(int64_t)b * 2048 + idx] + db;
    }
    // mean
    #pragma unroll
    for (int k = 0; k < 4; k++) {
        float s = y[k];
        #pragma unroll
        for (int o = 16; o; o >>= 1) s += __shfl_xor_sync(0xffffffffu, s, o);
        if (lane == 0) red[k][wrp] = s;
    }
    __syncthreads();
    if (hh < 4) {
        float s = 0.f;
        #pragma unroll
        for (int w = 0; w < 16; w++) s += red[hh][w];
        mu_s[hh] = s * (1.0f / H_);
    }
    __syncthreads();
    const float mu[4] = {mu_s[0], mu_s[1], mu_s[2], mu_s[3]};
    // variance (two-pass, matches reference)
    #pragma unroll
    for (int k = 0; k < 4; k++) {
        float d = y[k] - mu[k];
        float s = d * d;
        #pragma unroll
        for (int o = 16; o; o >>= 1) s += __shfl_xor_sync(0xffffffffu, s, o);
        if (lane == 0) red[k][wrp] = s;
    }
    __syncthreads();
    if (hh < 4) {
        float s = 0.f;
        #pragma unroll
        for (int w = 0; w < 16; w++) s += red[hh][w];
        iv_s[hh] = rsqrtf(s * (1.0f / H_) + 1e-5f);
    }
    __syncthreads();

    float yn[4];
    #pragma unroll
    for (int k = 0; k < 4; k++)
        yn[k] = (y[k] - mu[k]) * iv_s[k] * lng[k * H_ + hh] + lnb[k * H_ + hh];

    const float ig = 1.f / (1.f + expf(-yn[0]));
    const float fg = 1.f / (1.f + expf(-yn[1]));
    const float gg = tanhf(yn[2]);
    const float og = 1.f / (1.f + expf(-yn[3]));

    const int64_t bi = (int64_t)b * H_ + hh;
    const float cn = fg * c[bi] + ig * gg;
    const float hn = og * tanhf(cn);
    c[bi] = cn;  h[bi] = hn;  out[bi] = hn;
    if (hT) { hT[bi] = hn; cT[bi] = cn; }
}

// ---------------- host driver ----------------
extern "C" void kernel_launch(void* const* d_in, const int* in_sizes, int n_in,
                              void* d_out, int out_size)
{
    const float* x    = (const float*)d_in[0];
    const float* meta = (const float*)d_in[1];
    const int*   inp  = (const int*)  d_in[2];
    const float* Wq   = (const float*)d_in[3];
    const float* bq   = (const float*)d_in[4];
    const float* Wk   = (const float*)d_in[5];
    const float* bk   = (const float*)d_in[6];
    const float* Wm   = (const float*)d_in[7];
    const float* bm   = (const float*)d_in[8];
    const float* Wzh  = (const float*)d_in[9];
    const float* bzh  = (const float*)d_in[10];
    const float* Wzx  = (const float*)d_in[11];
    const float* bzx  = (const float*)d_in[12];
    const float* Wzb  = (const float*)d_in[13];
    const float* Wdh  = (const float*)d_in[14];
    const float* Wdx  = (const float*)d_in[15];
    const float* Wdb  = (const float*)d_in[16];
    const float* bdb  = (const float*)d_in[17];
    const float* w_h  = (const float*)d_in[18];
    const float* w_x  = (const float*)d_in[19];
    const float* lng  = (const float*)d_in[20];
    const float* lnb  = (const float*)d_in[21];
    float* out = (float*)d_out;

    float *pq, *pk, *patt, *pmpre, *pwx, *pWzT, *pWcomp, *pbcomp,
          *pmerged, *pD, *pwh, *ph, *pc;
    cudaGetSymbolAddress((void**)&pq,     g_q);
    cudaGetSymbolAddress((void**)&pk,     g_k);
    cudaGetSymbolAddress((void**)&patt,   g_att);
    cudaGetSymbolAddress((void**)&pmpre,  g_mpre);
    cudaGetSymbolAddress((void**)&pwx,    g_wx);
    cudaGetSymbolAddress((void**)&pWzT,   g_WzT);
    cudaGetSymbolAddress((void**)&pWcomp, g_Wcomp);
    cudaGetSymbolAddress((void**)&pbcomp, g_bcomp);
    cudaGetSymbolAddress((void**)&pmerged,g_merged);
    cudaGetSymbolAddress((void**)&pD,     g_D);
    cudaGetSymbolAddress((void**)&pwh,    g_wh);
    cudaGetSymbolAddress((void**)&ph,     g_h);
    cudaGetSymbolAddress((void**)&pc,     g_c);

    // init h=c=0, zero the trailing h_hat block of the output
    init_zero<<<1024, 256>>>(ph, pc, out + OFF_HHAT);

    // ---- weight preprocessing ----
    transpose_wz<<<3072, 256>>>(Wzh, Wzx, Wzb, pWzT);
    {   // Wcomp[s][k] (512x256) = Wd_s[k] (512x256) @ WzT_s[k]^T-form
        dim3 gW(HYP_ / BN, H_ / BM, 4);
        const float* Wd[3] = {Wdh, Wdx, Wdb};
        for (int s = 0; s < 3; s++)
            sgemm_nt<<<gW, 256>>>(Wd[s], HYP_, (int64_t)H_ * HYP_,
                                  pWzT + (int64_t)s * 4 * HYP_ * HYP_, HYP_, (int64_t)HYP_ * HYP_,
                                  pWcomp + (int64_t)s * 4 * H_ * HYP_, HYP_, (int64_t)H_ * HYP_,
                                  nullptr, nullptr, 0, HYP_, 0);
    }
    comp_bias<<<24, 256>>>(bzh, Wdh, bzx, Wdx, bdb, pbcomp);

    // ---- parallel (state-independent) phase ----
    // q = x @ Wq^T + bq
    sgemm_nt<<<dim3(HYP_ / BN, (T_ * B_) / BM, 1), 256>>>(
        x, DIN_, 0, Wq, DIN_, 0, pq, HYP_, 0, bq, nullptr, 0, DIN_, 0);
    // k = meta @ Wk^T + bk
    sgemm_nt<<<dim3(HYP_ / BN, (B_ * L_) / BM, 1), 256>>>(
        meta, DM_, 0, Wk, DM_, 0, pk, HYP_, 0, bk, nullptr, 0, DM_, 0);
    // attention: scores -> mask -> softmax -> attended
    attn_kernel<<<T_ * B_, 256>>>(pq, pk, meta, inp, patt);
    // mergedpre = x @ Wm[:, :512]^T + bm
    sgemm_nt<<<dim3(HYP_ / BN, (T_ * B_) / BM, 1), 256>>>(
        x, DIN_, 0, Wm, DIN_ + DM_ + H_, 0, pmpre, HYP_, 0, bm, nullptr, 0, DIN_, 0);
    // mergedpre += attended @ Wm[:, 512:768]^T
    sgemm_nt<<<dim3(HYP_ / BN, (T_ * B_) / BM, 1), 256>>>(
        patt, DM_, 0, Wm + DIN_, DIN_ + DM_ + H_, 0, pmpre, HYP_, 0,
        nullptr, pmpre, HYP_, DM_, 0);
    // wx_all = x @ w_x^T  (T*B, 2048)
    sgemm_nt<<<dim3((4 * H_) / BN, (T_ * B_) / BM, 1), 256>>>(
        x, DIN_, 0, w_x, DIN_, 0, pwx, 4 * H_, 0, nullptr, nullptr, 0, DIN_, 0);

    // ---- sequential scan ----
    for (int t = 0; t < T_; t++) {
        // merged = relu(mergedpre[t] + h @ Wm[:, 768:]^T)
        sgemm_nt<<<dim3(HYP_ / BN, B_ / BM, 1), 256>>>(
            ph, H_, 0, Wm + DIN_ + DM_, DIN_ + DM_ + H_, 0, pmerged, HYP_, 0,
            nullptr, pmpre + (int64_t)t * B_ * HYP_, HYP_, H_, 1);
        // D = merged @ Wcomp^T + bcomp   (B x 6144 = [s][k][h])
        sgemm_nt<<<dim3((3 * 4 * H_) / BN, B_ / BM, 1), 256>>>(
            pmerged, HYP_, 0, pWcomp, HYP_, 0, pD, 3 * 4 * H_, 0,
            pbcomp, nullptr, 0, HYP_, 0);
        // wh = h @ w_h^T   (B x 2048)
        sgemm_nt<<<dim3((4 * H_) / BN, B_ / BM, 1), 256>>>(
            ph, H_, 0, w_h, H_, 0, pwh, 4 * H_, 0, nullptr, nullptr, 0, H_, 0);
        // y = d_h*wh + d_x*wx + d_b -> LN -> gates -> h,c update
        const bool last = (t == T_ - 1);
        lstm_step<<<B_, H_>>>(pD, pwh, pwx + (int64_t)t * B_ * 4 * H_, lng, lnb,
                              ph, pc, out + (int64_t)t * B_ * H_,
                              last ? out + OFF_HT : nullptr,
                              last ? out + OFF_CT : nullptr);
    }
}

// round 4
// speedup vs baseline: 1.1683x; 1.1683x over previous
#include <cuda_runtime.h>
#include <stdint.h>
#include <math.h>

// ---------------- problem constants ----------------
#define T_   128
#define B_   512
#define DIN_ 512
#define H_   512
#define DM_  256
#define HYP_ 256
#define L_   100

// output offsets (floats)
#define OUT_N      ((int64_t)T_*B_*H_)
#define OFF_HT     (OUT_N)
#define OFF_CT     (OFF_HT + (int64_t)B_*H_)
#define OFF_HHAT   (OFF_CT + (int64_t)B_*H_)

// ---------------- scratch (device globals) ----------------
__device__ float g_q   [(size_t)T_*B_*HYP_];
__device__ float g_k   [(size_t)B_*L_*HYP_];
__device__ float g_att [(size_t)T_*B_*DM_];
__device__ float g_mpre[(size_t)T_*B_*HYP_];
__device__ float g_wx  [(size_t)T_*B_*4*H_];
__device__ float g_WzT [3*4*HYP_*HYP_];
__device__ float g_Wcomp[3*4*H_*HYP_];
__device__ float g_bcomp[3*4*H_];
__device__ float g_merged[B_*HYP_];
__device__ float g_D  [(size_t)B_*3*4*H_];
__device__ float g_wh [(size_t)B_*4*H_];
__device__ float g_h  [B_*H_];
__device__ float g_c  [B_*H_];

// ---------------- packed f32x2 helpers (sm_100+) ----------------
typedef unsigned long long u64;

__device__ __forceinline__ u64 dup2f(float a) {
    u64 r; asm("mov.b64 %0, {%1, %1};" : "=l"(r) : "f"(a)); return r;
}
__device__ __forceinline__ void fma2(u64 &c, u64 a, u64 b) {
    asm("fma.rn.f32x2 %0, %1, %2, %0;" : "+l"(c) : "l"(a), "l"(b));
}
__device__ __forceinline__ void unpk(u64 v, float &lo, float &hi) {
    asm("mov.b64 {%0, %1}, %2;" : "=f"(lo), "=f"(hi) : "l"(v));
}

// ---------------- 128x128x16 double-buffered FFMA2 GEMM core ----------------
// C[m,n] = sum_k A[m,k] * W[n,k]  (+bias[n]) (+addsrc[m,n]) (relu)
__device__ __forceinline__ void gemm128_core(
    const float* __restrict__ A, int lda,
    const float* __restrict__ W, int ldw,
    float* __restrict__ C, int ldc,
    const float* __restrict__ bias,
    const float* __restrict__ addsrc, int ldadd,
    int K, int relu, int64_t m0, int n0,
    float (*As)[16][128], float (*Ws)[16][128])
{
    const int tid = threadIdx.x;
    const int lr = tid >> 1;               // 0..127
    const int lk = (tid & 1) << 3;         // 0 or 8
    const float* Ap = A + (m0 + lr) * (int64_t)lda + lk;
    const float* Wp = W + (int64_t)(n0 + lr) * ldw + lk;
    const int tx = tid & 15, ty = tid >> 4;

    u64 acc[8][4];
    #pragma unroll
    for (int i = 0; i < 8; i++)
        #pragma unroll
        for (int j = 0; j < 4; j++) acc[i][j] = 0ull;

    float4 pa0 = *(const float4*)(Ap);
    float4 pa1 = *(const float4*)(Ap + 4);
    float4 pw0 = *(const float4*)(Wp);
    float4 pw1 = *(const float4*)(Wp + 4);

    As[0][lk+0][lr]=pa0.x; As[0][lk+1][lr]=pa0.y; As[0][lk+2][lr]=pa0.z; As[0][lk+3][lr]=pa0.w;
    As[0][lk+4][lr]=pa1.x; As[0][lk+5][lr]=pa1.y; As[0][lk+6][lr]=pa1.z; As[0][lk+7][lr]=pa1.w;
    Ws[0][lk+0][lr]=pw0.x; Ws[0][lk+1][lr]=pw0.y; Ws[0][lk+2][lr]=pw0.z; Ws[0][lk+3][lr]=pw0.w;
    Ws[0][lk+4][lr]=pw1.x; Ws[0][lk+5][lr]=pw1.y; Ws[0][lk+6][lr]=pw1.z; Ws[0][lk+7][lr]=pw1.w;
    __syncthreads();

    int buf = 0;
    for (int k0 = 0; k0 < K; k0 += 16) {
        const bool more = (k0 + 16) < K;
        if (more) {
            pa0 = *(const float4*)(Ap + k0 + 16);
            pa1 = *(const float4*)(Ap + k0 + 20);
            pw0 = *(const float4*)(Wp + k0 + 16);
            pw1 = *(const float4*)(Wp + k0 + 20);
        }
        #pragma unroll
        for (int kk = 0; kk < 16; kk++) {
            float4 a0 = *(const float4*)&As[buf][kk][ty << 3];
            float4 a1 = *(const float4*)&As[buf][kk][(ty << 3) + 4];
            const u64* bp = (const u64*)&Ws[buf][kk][tx << 3];
            u64 b0 = bp[0], b1 = bp[1], b2 = bp[2], b3 = bp[3];
            float am[8] = {a0.x, a0.y, a0.z, a0.w, a1.x, a1.y, a1.z, a1.w};
            #pragma unroll
            for (int i = 0; i < 8; i++) {
                u64 ad = dup2f(am[i]);
                fma2(acc[i][0], ad, b0);
                fma2(acc[i][1], ad, b1);
                fma2(acc[i][2], ad, b2);
                fma2(acc[i][3], ad, b3);
            }
        }
        if (more) {
            const int nb = buf ^ 1;
            As[nb][lk+0][lr]=pa0.x; As[nb][lk+1][lr]=pa0.y; As[nb][lk+2][lr]=pa0.z; As[nb][lk+3][lr]=pa0.w;
            As[nb][lk+4][lr]=pa1.x; As[nb][lk+5][lr]=pa1.y; As[nb][lk+6][lr]=pa1.z; As[nb][lk+7][lr]=pa1.w;
            Ws[nb][lk+0][lr]=pw0.x; Ws[nb][lk+1][lr]=pw0.y; Ws[nb][lk+2][lr]=pw0.z; Ws[nb][lk+3][lr]=pw0.w;
            Ws[nb][lk+4][lr]=pw1.x; Ws[nb][lk+5][lr]=pw1.y; Ws[nb][lk+6][lr]=pw1.z; Ws[nb][lk+7][lr]=pw1.w;
            __syncthreads();
            buf = nb;
        }
    }

    const int nc = n0 + (tx << 3);
    float bv[8];
    if (bias) {
        float4 q0 = *(const float4*)&bias[nc];
        float4 q1 = *(const float4*)&bias[nc + 4];
        bv[0]=q0.x; bv[1]=q0.y; bv[2]=q0.z; bv[3]=q0.w;
        bv[4]=q1.x; bv[5]=q1.y; bv[6]=q1.z; bv[7]=q1.w;
    } else {
        #pragma unroll
        for (int j = 0; j < 8; j++) bv[j] = 0.f;
    }
    #pragma unroll
    for (int i = 0; i < 8; i++) {
        const int64_t row = m0 + (ty << 3) + i;
        float r[8];
        #pragma unroll
        for (int p = 0; p < 4; p++) {
            float lo, hi; unpk(acc[i][p], lo, hi);
            r[2*p]   = lo + bv[2*p];
            r[2*p+1] = hi + bv[2*p+1];
        }
        if (addsrc) {
            const float* s = addsrc + row * (int64_t)ldadd + nc;
            float4 s0 = *(const float4*)s, s1 = *(const float4*)(s + 4);
            r[0]+=s0.x; r[1]+=s0.y; r[2]+=s0.z; r[3]+=s0.w;
            r[4]+=s1.x; r[5]+=s1.y; r[6]+=s1.z; r[7]+=s1.w;
        }
        if (relu) {
            #pragma unroll
            for (int j = 0; j < 8; j++) r[j] = fmaxf(r[j], 0.f);
        }
        float4 o0 = make_float4(r[0], r[1], r[2], r[3]);
        float4 o1 = make_float4(r[4], r[5], r[6], r[7]);
        *(float4*)&C[row * (int64_t)ldc + nc]     = o0;
        *(float4*)&C[row * (int64_t)ldc + nc + 4] = o1;
    }
}

__global__ void __launch_bounds__(256, 2)
sgemm128(const float* __restrict__ A, int lda, int64_t sA,
         const float* __restrict__ W, int ldw, int64_t sW,
         float* __restrict__ C, int ldc, int64_t sC,
         const float* __restrict__ bias,
         const float* __restrict__ addsrc, int ldadd,
         int K, int relu)
{
    __shared__ float As[2][16][128];
    __shared__ float Ws[2][16][128];
    const int bz = blockIdx.z;
    gemm128_core(A + bz * sA, lda, W + bz * sW, ldw, C + bz * sC, ldc,
                 bias, addsrc, ldadd, K, relu,
                 (int64_t)blockIdx.y * 128, blockIdx.x * 128, As, Ws);
}

// combined per-step kernel: wh = h @ w_h^T  |  D = merged @ Wcomp^T + bcomp
// wh tiles first (bx<16): they are 2x heavier (K=512), start them early.
__global__ void __launch_bounds__(256, 2)
sgemm_dwh(const float* __restrict__ h, const float* __restrict__ w_h,
          const float* __restrict__ merged, const float* __restrict__ Wcomp,
          const float* __restrict__ bcomp,
          float* __restrict__ wh, float* __restrict__ D)
{
    __shared__ float As[2][16][128];
    __shared__ float Ws[2][16][128];
    const int bx = blockIdx.x;
    const int64_t m0 = (int64_t)blockIdx.y * 128;
    if (bx < 16) {
        gemm128_core(h, H_, w_h, H_, wh, 4*H_, nullptr, nullptr, 0,
                     H_, 0, m0, bx * 128, As, Ws);
    } else {
        gemm128_core(merged, HYP_, Wcomp, HYP_, D, 3*4*H_, bcomp, nullptr, 0,
                     HYP_, 0, m0, (bx - 16) * 128, As, Ws);
    }
}

// ---------------- small GEMM for merged = relu(mpre + h @ Wm3^T) ----------------
// 32x64 tile, 128 threads, micro 4x4, double-buffered. grid (4, 16) = 64 blocks.
__global__ void __launch_bounds__(128)
sgemm_merged(const float* __restrict__ h, const float* __restrict__ Wm3,
             const float* __restrict__ mpre, float* __restrict__ mg)
{
    __shared__ float As[2][16][32];
    __shared__ float Ws[2][16][64];
    const int n0 = blockIdx.x << 6;
    const int m0 = blockIdx.y << 5;
    const int tid = threadIdx.x;
    const int ar = tid >> 2, ak = (tid & 3) << 2;
    const int wr = tid >> 1, wk = (tid & 1) << 3;
    const float* Ap = h + (m0 + ar) * H_ + ak;
    const float* Wp = Wm3 + (int64_t)(n0 + wr) * (DIN_ + DM_ + H_) + wk;
    const int tx = tid & 15, ty = tid >> 4;

    float acc[4][4] = {};
    float4 a  = *(const float4*)(Ap);
    float4 w0 = *(const float4*)(Wp);
    float4 w1 = *(const float4*)(Wp + 4);
    As[0][ak+0][ar]=a.x; As[0][ak+1][ar]=a.y; As[0][ak+2][ar]=a.z; As[0][ak+3][ar]=a.w;
    Ws[0][wk+0][wr]=w0.x; Ws[0][wk+1][wr]=w0.y; Ws[0][wk+2][wr]=w0.z; Ws[0][wk+3][wr]=w0.w;
    Ws[0][wk+4][wr]=w1.x; Ws[0][wk+5][wr]=w1.y; Ws[0][wk+6][wr]=w1.z; Ws[0][wk+7][wr]=w1.w;
    __syncthreads();

    int buf = 0;
    for (int k0 = 0; k0 < H_; k0 += 16) {
        const bool more = (k0 + 16) < H_;
        if (more) {
            a  = *(const float4*)(Ap + k0 + 16);
            w0 = *(const float4*)(Wp + k0 + 16);
            w1 = *(const float4*)(Wp + k0 + 20);
        }
        #pragma unroll
        for (int kk = 0; kk < 16; kk++) {
            float4 av = *(const float4*)&As[buf][kk][ty << 2];
            float4 wv = *(const float4*)&Ws[buf][kk][tx << 2];
            float am[4] = {av.x, av.y, av.z, av.w};
            float wn[4] = {wv.x, wv.y, wv.z, wv.w};
            #pragma unroll
            for (int i = 0; i < 4; i++)
                #pragma unroll
                for (int j = 0; j < 4; j++)
                    acc[i][j] += am[i] * wn[j];
        }
        if (more) {
            const int nb = buf ^ 1;
            As[nb][ak+0][ar]=a.x; As[nb][ak+1][ar]=a.y; As[nb][ak+2][ar]=a.z; As[nb][ak+3][ar]=a.w;
            Ws[nb][wk+0][wr]=w0.x; Ws[nb][wk+1][wr]=w0.y; Ws[nb][wk+2][wr]=w0.z; Ws[nb][wk+3][wr]=w0.w;
            Ws[nb][wk+4][wr]=w1.x; Ws[nb][wk+5][wr]=w1.y; Ws[nb][wk+6][wr]=w1.z; Ws[nb][wk+7][wr]=w1.w;
            __syncthreads();
            buf = nb;
        }
    }
    const int nc = n0 + (tx << 2);
    #pragma unroll
    for (int i = 0; i < 4; i++) {
        const int row = m0 + (ty << 2) + i;
        float4 s = *(const float4*)&mpre[row * HYP_ + nc];
        float4 r;
        r.x = fmaxf(acc[i][0] + s.x, 0.f);
        r.y = fmaxf(acc[i][1] + s.y, 0.f);
        r.z = fmaxf(acc[i][2] + s.z, 0.f);
        r.w = fmaxf(acc[i][3] + s.w, 0.f);
        *(float4*)&mg[row * HYP_ + nc] = r;
    }
}

// ---------------- fused attention ----------------
__global__ void __launch_bounds__(256)
attn_kernel(const float* __restrict__ q, const float* __restrict__ k,
            const float* __restrict__ meta, const int* __restrict__ inp,
            float* __restrict__ att)
{
    const int tb = blockIdx.x;
    const int b  = tb & (B_ - 1);
    const int tid = threadIdx.x;
    __shared__ float qs[HYP_];
    __shared__ float sc[128];

    qs[tid] = q[(int64_t)tb * HYP_ + tid] * 0.0625f;
    __syncthreads();

    const int lane = tid & 31, wrp = tid >> 5;
    for (int l = wrp; l < L_; l += 8) {
        const float* kp = k + ((int64_t)b * L_ + l) * HYP_;
        float s = 0.f;
        #pragma unroll
        for (int e = 0; e < HYP_ / 32; e++)
            s += qs[lane + 32 * e] * kp[lane + 32 * e];
        #pragma unroll
        for (int o = 16; o; o >>= 1) s += __shfl_xor_sync(0xffffffffu, s, o);
        if (lane == 0) sc[l] = (inp[b * L_ + l] == 0) ? -1e9f : s;
    }
    __syncthreads();

    if (tid < 32) {
        float v[4]; float m = -3.0e38f;
        #pragma unroll
        for (int j = 0; j < 4; j++) {
            int l = tid + 32 * j;
            v[j] = (l < L_) ? sc[l] : -3.0e38f;
            m = fmaxf(m, v[j]);
        }
        #pragma unroll
        for (int o = 16; o; o >>= 1) m = fmaxf(m, __shfl_xor_sync(0xffffffffu, m, o));
        float s = 0.f;
        #pragma unroll
        for (int j = 0; j < 4; j++) { v[j] = expf(v[j] - m); s += v[j]; }
        #pragma unroll
        for (int o = 16; o; o >>= 1) s += __shfl_xor_sync(0xffffffffu, s, o);
        const float inv = 1.0f / s;
        #pragma unroll
        for (int j = 0; j < 4; j++) {
            int l = tid + 32 * j;
            if (l < L_) sc[l] = v[j] * inv;
        }
    }
    __syncthreads();

    float acc = 0.f;
    const float* mp = meta + (int64_t)b * L_ * DM_ + tid;
    #pragma unroll 4
    for (int l = 0; l < L_; l++) acc += sc[l] * mp[(int64_t)l * DM_];
    att[(int64_t)tb * DM_ + tid] = acc;
}

// ---------------- weight preprocessing ----------------
__global__ void transpose_wz(const float* __restrict__ Wzh, const float* __restrict__ Wzx,
                             const float* __restrict__ Wzb, float* __restrict__ WzT)
{
    int idx = blockIdx.x * 256 + threadIdx.x;
    int s  = idx / (4 * HYP_ * HYP_);
    int r  = idx % (4 * HYP_ * HYP_);
    int kk = r / (HYP_ * HYP_);
    int r2 = r % (HYP_ * HYP_);
    int z  = r2 / HYP_;
    int z2 = r2 % HYP_;
    const float* Wz = (s == 0) ? Wzh : ((s == 1) ? Wzx : Wzb);
    WzT[idx] = Wz[(kk * HYP_ + z2) * HYP_ + z];
}

__global__ void comp_bias(const float* __restrict__ bzh, const float* __restrict__ Wdh,
                          const float* __restrict__ bzx, const float* __restrict__ Wdx,
                          const float* __restrict__ bdb, float* __restrict__ bcomp)
{
    int n = blockIdx.x * 256 + threadIdx.x;
    if (n < 2048) {
        int kk = n >> 9;
        float s = 0.f;
        for (int z = 0; z < HYP_; z++) s += bzh[kk * HYP_ + z] * Wdh[n * HYP_ + z];
        bcomp[n] = s;
    } else if (n < 4096) {
        int m = n - 2048; int kk = m >> 9;
        float s = 0.f;
        for (int z = 0; z < HYP_; z++) s += bzx[kk * HYP_ + z] * Wdx[m * HYP_ + z];
        bcomp[n] = s;
    } else {
        bcomp[n] = bdb[n - 4096];
    }
}

__global__ void init_zero(float* __restrict__ h, float* __restrict__ c,
                          float* __restrict__ tail)
{
    int i = blockIdx.x * 256 + threadIdx.x;
    h[i] = 0.f; c[i] = 0.f; tail[i] = 0.f;
}

// ---------------- fused elementwise + LayerNorm + LSTM cell ----------------
__global__ void __launch_bounds__(512)
lstm_step(const float* __restrict__ D, const float* __restrict__ wh,
          const float* __restrict__ wx, const float* __restrict__ lng,
          const float* __restrict__ lnb, float* __restrict__ h,
          float* __restrict__ c, float* __restrict__ out,
          float* __restrict__ hT, float* __restrict__ cT)
{
    const int b  = blockIdx.x;
    const int hh = threadIdx.x;
    const int lane = hh & 31, wrp = hh >> 5;
    __shared__ float red[4][16];
    __shared__ float mu_s[4], iv_s[4];

    float y[4];
    #pragma unroll
    for (int k = 0; k < 4; k++) {
        const int idx = k * H_ + hh;
        const int64_t base = (int64_t)b * 6144;
        float dh = D[base + idx];
        float dx = D[base + 2048 + idx];
        float db = D[base + 4096 + idx];
        y[k] = dh * wh[(int64_t)b * 2048 + idx] + dx * wx[(int64_t)b * 2048 + idx] + db;
    }
    #pragma unroll
    for (int k = 0; k < 4; k++) {
        float s = y[k];
        #pragma unroll
        for (int o = 16; o; o >>= 1) s += __shfl_xor_sync(0xffffffffu, s, o);
        if (lane == 0) red[k][wrp] = s;
    }
    __syncthreads();
    if (hh < 4) {
        float s = 0.f;
        #pragma unroll
        for (int w = 0; w < 16; w++) s += red[hh][w];
        mu_s[hh] = s * (1.0f / H_);
    }
    __syncthreads();
    const float mu[4] = {mu_s[0], mu_s[1], mu_s[2], mu_s[3]};
    #pragma unroll
    for (int k = 0; k < 4; k++) {
        float d = y[k] - mu[k];
        float s = d * d;
        #pragma unroll
        for (int o = 16; o; o >>= 1) s += __shfl_xor_sync(0xffffffffu, s, o);
        if (lane == 0) red[k][wrp] = s;
    }
    __syncthreads();
    if (hh < 4) {
        float s = 0.f;
        #pragma unroll
        for (int w = 0; w < 16; w++) s += red[hh][w];
        iv_s[hh] = rsqrtf(s * (1.0f / H_) + 1e-5f);
    }
    __syncthreads();

    float yn[4];
    #pragma unroll
    for (int k = 0; k < 4; k++)
        yn[k] = (y[k] - mu[k]) * iv_s[k] * lng[k * H_ + hh] + lnb[k * H_ + hh];

    const float ig = 1.f / (1.f + expf(-yn[0]));
    const float fg = 1.f / (1.f + expf(-yn[1]));
    const float gg = tanhf(yn[2]);
    const float og = 1.f / (1.f + expf(-yn[3]));

    const int64_t bi = (int64_t)b * H_ + hh;
    const float cn = fg * c[bi] + ig * gg;
    const float hn = og * tanhf(cn);
    c[bi] = cn;  h[bi] = hn;  out[bi] = hn;
    if (hT) { hT[bi] = hn; cT[bi] = cn; }
}

// ---------------- host driver ----------------
extern "C" void kernel_launch(void* const* d_in, const int* in_sizes, int n_in,
                              void* d_out, int out_size)
{
    const float* x    = (const float*)d_in[0];
    const float* meta = (const float*)d_in[1];
    const int*   inp  = (const int*)  d_in[2];
    const float* Wq   = (const float*)d_in[3];
    const float* bq   = (const float*)d_in[4];
    const float* Wk   = (const float*)d_in[5];
    const float* bk   = (const float*)d_in[6];
    const float* Wm   = (const float*)d_in[7];
    const float* bm   = (const float*)d_in[8];
    const float* Wzh  = (const float*)d_in[9];
    const float* bzh  = (const float*)d_in[10];
    const float* Wzx  = (const float*)d_in[11];
    const float* bzx  = (const float*)d_in[12];
    const float* Wzb  = (const float*)d_in[13];
    const float* Wdh  = (const float*)d_in[14];
    const float* Wdx  = (const float*)d_in[15];
    const float* Wdb  = (const float*)d_in[16];
    const float* bdb  = (const float*)d_in[17];
    const float* w_h  = (const float*)d_in[18];
    const float* w_x  = (const float*)d_in[19];
    const float* lng  = (const float*)d_in[20];
    const float* lnb  = (const float*)d_in[21];
    float* out = (float*)d_out;

    float *pq, *pk, *patt, *pmpre, *pwx, *pWzT, *pWcomp, *pbcomp,
          *pmerged, *pD, *pwh, *ph, *pc;
    cudaGetSymbolAddress((void**)&pq,     g_q);
    cudaGetSymbolAddress((void**)&pk,     g_k);
    cudaGetSymbolAddress((void**)&patt,   g_att);
    cudaGetSymbolAddress((void**)&pmpre,  g_mpre);
    cudaGetSymbolAddress((void**)&pwx,    g_wx);
    cudaGetSymbolAddress((void**)&pWzT,   g_WzT);
    cudaGetSymbolAddress((void**)&pWcomp, g_Wcomp);
    cudaGetSymbolAddress((void**)&pbcomp, g_bcomp);
    cudaGetSymbolAddress((void**)&pmerged,g_merged);
    cudaGetSymbolAddress((void**)&pD,     g_D);
    cudaGetSymbolAddress((void**)&pwh,    g_wh);
    cudaGetSymbolAddress((void**)&ph,     g_h);
    cudaGetSymbolAddress((void**)&pc,     g_c);

    init_zero<<<1024, 256>>>(ph, pc, out + OFF_HHAT);

    // ---- weight preprocessing ----
    transpose_wz<<<3072, 256>>>(Wzh, Wzx, Wzb, pWzT);
    {
        dim3 gW(HYP_ / 128, H_ / 128, 4);
        const float* Wd[3] = {Wdh, Wdx, Wdb};
        for (int s = 0; s < 3; s++)
            sgemm128<<<gW, 256>>>(Wd[s], HYP_, (int64_t)H_ * HYP_,
                                  pWzT + (int64_t)s * 4 * HYP_ * HYP_, HYP_, (int64_t)HYP_ * HYP_,
                                  pWcomp + (int64_t)s * 4 * H_ * HYP_, HYP_, (int64_t)H_ * HYP_,
                                  nullptr, nullptr, 0, HYP_, 0);
    }
    comp_bias<<<24, 256>>>(bzh, Wdh, bzx, Wdx, bdb, pbcomp);

    // ---- parallel (state-independent) phase ----
    // q = x @ Wq^T + bq
    sgemm128<<<dim3(HYP_/128, (T_*B_)/128, 1), 256>>>(
        x, DIN_, 0, Wq, DIN_, 0, pq, HYP_, 0, bq, nullptr, 0, DIN_, 0);
    // k = meta @ Wk^T + bk
    sgemm128<<<dim3(HYP_/128, (B_*L_)/128, 1), 256>>>(
        meta, DM_, 0, Wk, DM_, 0, pk, HYP_, 0, bk, nullptr, 0, DM_, 0);
    // attention
    attn_kernel<<<T_ * B_, 256>>>(pq, pk, meta, inp, patt);
    // mergedpre = x @ Wm[:, :512]^T + bm
    sgemm128<<<dim3(HYP_/128, (T_*B_)/128, 1), 256>>>(
        x, DIN_, 0, Wm, DIN_ + DM_ + H_, 0, pmpre, HYP_, 0, bm, nullptr, 0, DIN_, 0);
    // mergedpre += attended @ Wm[:, 512:768]^T
    sgemm128<<<dim3(HYP_/128, (T_*B_)/128, 1), 256>>>(
        patt, DM_, 0, Wm + DIN_, DIN_ + DM_ + H_, 0, pmpre, HYP_, 0,
        nullptr, pmpre, HYP_, DM_, 0);
    // wx_all = x @ w_x^T  (T*B, 2048)
    sgemm128<<<dim3((4*H_)/128, (T_*B_)/128, 1), 256>>>(
        x, DIN_, 0, w_x, DIN_, 0, pwx, 4 * H_, 0, nullptr, nullptr, 0, DIN_, 0);

    // ---- sequential scan: 3 launches per step ----
    for (int t = 0; t < T_; t++) {
        // merged = relu(mergedpre[t] + h @ Wm[:, 768:]^T)
        sgemm_merged<<<dim3(4, 16), 128>>>(ph, Wm + DIN_ + DM_,
                                           pmpre + (int64_t)t * B_ * HYP_, pmerged);
        // wh = h @ w_h^T  |  D = merged @ Wcomp^T + bcomp
        sgemm_dwh<<<dim3(64, B_/128), 256>>>(ph, w_h, pmerged, pWcomp, pbcomp, pwh, pD);
        // elementwise + LN + LSTM cell
        const bool last = (t == T_ - 1);
        lstm_step<<<B_, H_>>>(pD, pwh, pwx + (int64_t)t * B_ * 4 * H_, lng, lnb,
                              ph, pc, out + (int64_t)t * B_ * H_,
                              last ? out + OFF_HT : nullptr,
                              last ? out + OFF_CT : nullptr);
    }
}